// round 1
// baseline (speedup 1.0000x reference)
#include <cuda_runtime.h>

#define B_   2
#define S_   2048
#define H_   1024
#define NH_  16
#define HD_  64
#define M_   (B_ * S_)

#define BR   128
#define BC   64
#define PAD  65

// Scratch for projected Q/K/V (allocation-free rule: __device__ globals)
__device__ float g_Q[M_ * H_];
__device__ float g_K[M_ * H_];
__device__ float g_V[M_ * H_];

// ---------------------------------------------------------------------------
// Fused QKV projection: C = A[4096,1024] @ W[1024,1024] + bias
// blockIdx.z selects {Q,K,V}. Classic 128x128x8 SGEMM, 8x8 per-thread tile.
// ---------------------------------------------------------------------------
__global__ __launch_bounds__(256) void qkv_gemm_kernel(
    const float* __restrict__ q, const float* __restrict__ k,
    const float* __restrict__ v,
    const float* __restrict__ wq, const float* __restrict__ bq,
    const float* __restrict__ wk, const float* __restrict__ bk,
    const float* __restrict__ wv, const float* __restrict__ bv)
{
    const int K = H_, N = H_;
    const int which = blockIdx.z;
    const float* A    = (which == 0) ? q  : (which == 1) ? k  : v;
    const float* W    = (which == 0) ? wq : (which == 1) ? wk : wv;
    const float* bias = (which == 0) ? bq : (which == 1) ? bk : bv;
    float* C          = (which == 0) ? g_Q : (which == 1) ? g_K : g_V;

    __shared__ float As[8][128];
    __shared__ float Bs[8][128];

    const int tid = threadIdx.x;
    const int bm = blockIdx.y * 128, bn = blockIdx.x * 128;
    const int tm = (tid >> 4) * 8, tn = (tid & 15) * 8;

    const int arow = tid >> 1,  acol = (tid & 1) * 4;
    const int brow = tid >> 5,  bcol = (tid & 31) * 4;

    const float* Aptr = A + (size_t)(bm + arow) * K + acol;
    const float* Wptr = W + (size_t)brow * N + bn + bcol;

    float acc[8][8] = {};

    for (int kt = 0; kt < K; kt += 8) {
        float4 av = *(const float4*)(Aptr + kt);
        float4 wv4 = *(const float4*)(Wptr + (size_t)kt * N);
        As[acol + 0][arow] = av.x;
        As[acol + 1][arow] = av.y;
        As[acol + 2][arow] = av.z;
        As[acol + 3][arow] = av.w;
        *(float4*)&Bs[brow][bcol] = wv4;
        __syncthreads();

        #pragma unroll
        for (int kk = 0; kk < 8; kk++) {
            float ra[8], rb[8];
            *(float4*)&ra[0] = *(const float4*)&As[kk][tm];
            *(float4*)&ra[4] = *(const float4*)&As[kk][tm + 4];
            *(float4*)&rb[0] = *(const float4*)&Bs[kk][tn];
            *(float4*)&rb[4] = *(const float4*)&Bs[kk][tn + 4];
            #pragma unroll
            for (int i = 0; i < 8; i++)
                #pragma unroll
                for (int j = 0; j < 8; j++)
                    acc[i][j] = fmaf(ra[i], rb[j], acc[i][j]);
        }
        __syncthreads();
    }

    #pragma unroll
    for (int i = 0; i < 8; i++) {
        #pragma unroll
        for (int j = 0; j < 8; j += 4) {
            float4 o;
            o.x = acc[i][j + 0] + bias[bn + tn + j + 0];
            o.y = acc[i][j + 1] + bias[bn + tn + j + 1];
            o.z = acc[i][j + 2] + bias[bn + tn + j + 2];
            o.w = acc[i][j + 3] + bias[bn + tn + j + 3];
            *(float4*)&C[(size_t)(bm + tm + i) * N + bn + tn + j] = o;
        }
    }
}

// ---------------------------------------------------------------------------
// Flash attention: per (batch, head), Br=128 query rows per CTA, Bc=64 keys
// per tile, online softmax. NOTE: mask is provably a no-op here (it adds a
// constant per query row across all keys; softmax is shift-invariant).
// ---------------------------------------------------------------------------
extern __shared__ float smem_dyn[];

__global__ __launch_bounds__(256) void attn_kernel(float* __restrict__ out)
{
    float* Qs = smem_dyn;                 // BR x PAD
    float* Ks = Qs + BR * PAD;            // BC x PAD
    float* Vs = Ks + BC * PAD;            // BC x PAD
    float* Ps = Vs + BC * PAD;            // BR x PAD

    const int tid = threadIdx.x;
    const int tx = tid & 15;              // 16 threads across 64 cols (stride 16)
    const int ty = tid >> 4;              // 16 thread-rows, 8 q-rows each
    const int b = blockIdx.z, h = blockIdx.y;
    const int q0 = blockIdx.x * BR;
    const float scale = 0.03125f;         // 1/sqrt(1024)

    const float* Qg = g_Q + ((size_t)b * S_) * H_ + (size_t)h * HD_;
    const float* Kg = g_K + ((size_t)b * S_) * H_ + (size_t)h * HD_;
    const float* Vg = g_V + ((size_t)b * S_) * H_ + (size_t)h * HD_;

    // Load Q tile: BR x 64
    #pragma unroll
    for (int it = 0; it < BR / 16; it++) {
        int r = (tid >> 4) + it * 16;
        int c = (tid & 15) * 4;
        float4 qv = *(const float4*)&Qg[(size_t)(q0 + r) * H_ + c];
        Qs[r * PAD + c + 0] = qv.x;
        Qs[r * PAD + c + 1] = qv.y;
        Qs[r * PAD + c + 2] = qv.z;
        Qs[r * PAD + c + 3] = qv.w;
    }

    float o[8][4] = {};
    float mrow[8], lrow[8];
    #pragma unroll
    for (int i = 0; i < 8; i++) { mrow[i] = -1e30f; lrow[i] = 0.0f; }

    for (int kt = 0; kt < S_; kt += BC) {
        __syncthreads();  // previous PV reads done before K/V overwrite

        // Load K,V tiles: BC x 64 each
        #pragma unroll
        for (int it = 0; it < BC / 16; it++) {
            int r = (tid >> 4) + it * 16;
            int c = (tid & 15) * 4;
            float4 kv = *(const float4*)&Kg[(size_t)(kt + r) * H_ + c];
            Ks[r * PAD + c + 0] = kv.x;
            Ks[r * PAD + c + 1] = kv.y;
            Ks[r * PAD + c + 2] = kv.z;
            Ks[r * PAD + c + 3] = kv.w;
            float4 vv = *(const float4*)&Vg[(size_t)(kt + r) * H_ + c];
            Vs[r * PAD + c + 0] = vv.x;
            Vs[r * PAD + c + 1] = vv.y;
            Vs[r * PAD + c + 2] = vv.z;
            Vs[r * PAD + c + 3] = vv.w;
        }
        __syncthreads();

        // S = Q @ K^T  (8 rows x 4 cols per thread; cols interleaved stride 16)
        float s[8][4] = {};
        #pragma unroll 4
        for (int d = 0; d < HD_; d++) {
            float qa[8], kb[4];
            #pragma unroll
            for (int i = 0; i < 8; i++) qa[i] = Qs[(ty * 8 + i) * PAD + d];
            #pragma unroll
            for (int j = 0; j < 4; j++) kb[j] = Ks[(tx + 16 * j) * PAD + d];
            #pragma unroll
            for (int i = 0; i < 8; i++)
                #pragma unroll
                for (int j = 0; j < 4; j++)
                    s[i][j] = fmaf(qa[i], kb[j], s[i][j]);
        }

        // Online softmax update (row groups = 16 lanes, shfl-xor butterflies)
        #pragma unroll
        for (int i = 0; i < 8; i++) {
            #pragma unroll
            for (int j = 0; j < 4; j++) s[i][j] *= scale;
            float mt = fmaxf(fmaxf(s[i][0], s[i][1]), fmaxf(s[i][2], s[i][3]));
            #pragma unroll
            for (int off = 1; off < 16; off <<= 1)
                mt = fmaxf(mt, __shfl_xor_sync(0xffffffffu, mt, off));
            float mnew = fmaxf(mrow[i], mt);
            float corr = __expf(mrow[i] - mnew);
            mrow[i] = mnew;
            float rs = 0.0f;
            #pragma unroll
            for (int j = 0; j < 4; j++) {
                s[i][j] = __expf(s[i][j] - mnew);
                rs += s[i][j];
            }
            #pragma unroll
            for (int off = 1; off < 16; off <<= 1)
                rs += __shfl_xor_sync(0xffffffffu, rs, off);
            lrow[i] = lrow[i] * corr + rs;
            #pragma unroll
            for (int dd = 0; dd < 4; dd++) o[i][dd] *= corr;
            #pragma unroll
            for (int j = 0; j < 4; j++)
                Ps[(ty * 8 + i) * PAD + tx + 16 * j] = s[i][j];
        }
        __syncthreads();

        // O += P @ V
        #pragma unroll 4
        for (int j = 0; j < BC; j++) {
            float pv[8], vb[4];
            #pragma unroll
            for (int i = 0; i < 8; i++) pv[i] = Ps[(ty * 8 + i) * PAD + j];
            #pragma unroll
            for (int dd = 0; dd < 4; dd++) vb[dd] = Vs[j * PAD + tx + 16 * dd];
            #pragma unroll
            for (int i = 0; i < 8; i++)
                #pragma unroll
                for (int dd = 0; dd < 4; dd++)
                    o[i][dd] = fmaf(pv[i], vb[dd], o[i][dd]);
        }
    }

    // Epilogue: out[b, q0+r, h*64 + tx + 16*dd] = o / l
    #pragma unroll
    for (int i = 0; i < 8; i++) {
        float inv = 1.0f / lrow[i];
        int r = q0 + ty * 8 + i;
        #pragma unroll
        for (int dd = 0; dd < 4; dd++)
            out[((size_t)b * S_ + r) * H_ + (size_t)h * HD_ + tx + 16 * dd] =
                o[i][dd] * inv;
    }
}

// ---------------------------------------------------------------------------
extern "C" void kernel_launch(void* const* d_in, const int* in_sizes, int n_in,
                              void* d_out, int out_size)
{
    const float* q  = (const float*)d_in[0];
    const float* k  = (const float*)d_in[1];
    const float* v  = (const float*)d_in[2];
    // d_in[3] = mask: provably a no-op (uniform per-row shift under softmax)
    const float* wq = (const float*)d_in[4];
    const float* bq = (const float*)d_in[5];
    const float* wk = (const float*)d_in[6];
    const float* bk = (const float*)d_in[7];
    const float* wv = (const float*)d_in[8];
    const float* bv = (const float*)d_in[9];
    float* out = (float*)d_out;

    // QKV projections: grid z = {Q, K, V}
    dim3 gg(H_ / 128, M_ / 128, 3);
    qkv_gemm_kernel<<<gg, 256>>>(q, k, v, wq, bq, wk, bk, wv, bv);

    // Flash attention
    const int smem_bytes = (BR * PAD + BC * PAD + BC * PAD + BR * PAD) * 4;
    cudaFuncSetAttribute(attn_kernel,
                         cudaFuncAttributeMaxDynamicSharedMemorySize,
                         smem_bytes);
    dim3 ga(S_ / BR, NH_, B_);
    attn_kernel<<<ga, 256, smem_bytes>>>(out);
}

// round 3
// speedup vs baseline: 1.3259x; 1.3259x over previous
#include <cuda_runtime.h>
#include <cstdint>

#define B_   2
#define S_   2048
#define H_   1024
#define NH_  16
#define HD_  64
#define M_   (B_ * S_)

#define BR   128
#define BC   64
#define PAD  65

// GEMM tile config
#define TM   128
#define TN   128
#define KC   32
#define NCHUNK (H_ / KC)
#define SA_STR 36     // floats; bank = 4*row + col -> conflict-free fragments
#define SB_STR 136    // floats; bank = 8*k + col   -> conflict-free fragments

// Scratch for projected Q/K/V (allocation-free rule: __device__ globals)
__device__ float g_Q[M_ * H_];
__device__ float g_K[M_ * H_];
__device__ float g_V[M_ * H_];

__device__ __forceinline__ uint32_t to_tf32(float x) {
    float r;
    asm("cvt.rna.tf32.f32 %0, %1;" : "=f"(r) : "f"(x));
    return __float_as_uint(r);
}

__device__ __forceinline__ void mma_tf32(float c[4], uint32_t a0, uint32_t a1,
                                         uint32_t a2, uint32_t a3,
                                         uint32_t b0, uint32_t b1) {
    asm volatile(
        "mma.sync.aligned.m16n8k8.row.col.f32.tf32.tf32.f32 "
        "{%0,%1,%2,%3}, {%4,%5,%6,%7}, {%8,%9}, {%0,%1,%2,%3};"
        : "+f"(c[0]), "+f"(c[1]), "+f"(c[2]), "+f"(c[3])
        : "r"(a0), "r"(a1), "r"(a2), "r"(a3), "r"(b0), "r"(b1));
}

// ---------------------------------------------------------------------------
// Tensor-core tf32 GEMM: C[4096,1024] = A @ W + bias, blockIdx.z in {Q,K,V}
// CTA 128x128, 8 warps (2x4), warp tile 64x32 = 4x4 m16n8k8 MMAs.
// Double-buffered SMEM, KC=32 per chunk, one __syncthreads per chunk.
// ---------------------------------------------------------------------------
extern __shared__ char gsm[];

__global__ __launch_bounds__(256) void qkv_gemm_tc(
    const float* __restrict__ q, const float* __restrict__ k,
    const float* __restrict__ v,
    const float* __restrict__ wq, const float* __restrict__ bq,
    const float* __restrict__ wk, const float* __restrict__ bk,
    const float* __restrict__ wv, const float* __restrict__ bv)
{
    const int which = blockIdx.z;
    const float* A    = (which == 0) ? q  : (which == 1) ? k  : v;
    const float* W    = (which == 0) ? wq : (which == 1) ? wk : wv;
    const float* bias = (which == 0) ? bq : (which == 1) ? bk : bv;
    float* C          = (which == 0) ? g_Q : (which == 1) ? g_K : g_V;

    uint32_t* As = (uint32_t*)gsm;                       // [2][128*36]
    uint32_t* Bs = As + 2 * TM * SA_STR;                 // [2][32*136]

    const int tid = threadIdx.x;
    const int wid = tid >> 5, lid = tid & 31;
    const int g = lid >> 2, tig = lid & 3;               // group / thread-in-group
    const int wr = wid >> 2, wc = wid & 3;               // warp row/col in 2x4
    const int mrow0 = wr * 64, ncol0 = wc * 32;
    const int bm = blockIdx.y * TM, bn = blockIdx.x * TN;

    // loader indices
    const int am = tid >> 1;                 // with 2 iters -> rows, see below
    (void)am;

    float acc[4][4][4] = {};

    // -- cooperative chunk load: A[128x32] + B[32x128] (tf32-converted)
    auto load_global = [&](int c, float4 ra[4], float4 rb[4]) {
        const int k0 = c * KC;
        #pragma unroll
        for (int i = 0; i < 4; i++) {
            int li = tid + i * 256;
            int m = li >> 3, kg = li & 7;
            ra[i] = *(const float4*)&A[(size_t)(bm + m) * H_ + k0 + kg * 4];
            int kr = li >> 5, ng = li & 31;
            rb[i] = *(const float4*)&W[(size_t)(k0 + kr) * H_ + bn + ng * 4];
        }
    };
    auto store_smem = [&](int buf, const float4 ra[4], const float4 rb[4]) {
        uint32_t* sa = As + buf * TM * SA_STR;
        uint32_t* sb = Bs + buf * KC * SB_STR;
        #pragma unroll
        for (int i = 0; i < 4; i++) {
            int li = tid + i * 256;
            int m = li >> 3, kg = li & 7;
            uint32_t* pa = sa + m * SA_STR + kg * 4;
            pa[0] = to_tf32(ra[i].x); pa[1] = to_tf32(ra[i].y);
            pa[2] = to_tf32(ra[i].z); pa[3] = to_tf32(ra[i].w);
            int kr = li >> 5, ng = li & 31;
            uint32_t* pb = sb + kr * SB_STR + ng * 4;
            pb[0] = to_tf32(rb[i].x); pb[1] = to_tf32(rb[i].y);
            pb[2] = to_tf32(rb[i].z); pb[3] = to_tf32(rb[i].w);
        }
    };

    {
        float4 ra[4], rb[4];
        load_global(0, ra, rb);
        store_smem(0, ra, rb);
    }
    __syncthreads();

    for (int c = 0; c < NCHUNK; c++) {
        const int buf = c & 1;
        const uint32_t* sa = As + buf * TM * SA_STR;
        const uint32_t* sb = Bs + buf * KC * SB_STR;

        float4 ra[4], rb[4];
        if (c + 1 < NCHUNK) load_global(c + 1, ra, rb);

        #pragma unroll
        for (int kk = 0; kk < 4; kk++) {
            uint32_t af[4][4];
            #pragma unroll
            for (int mi = 0; mi < 4; mi++) {
                int r = mrow0 + mi * 16 + g;
                int cb = kk * 8 + tig;
                af[mi][0] = sa[r * SA_STR + cb];
                af[mi][1] = sa[(r + 8) * SA_STR + cb];
                af[mi][2] = sa[r * SA_STR + cb + 4];
                af[mi][3] = sa[(r + 8) * SA_STR + cb + 4];
            }
            uint32_t bf[4][2];
            #pragma unroll
            for (int ni = 0; ni < 4; ni++) {
                int col = ncol0 + ni * 8 + g;
                bf[ni][0] = sb[(kk * 8 + tig) * SB_STR + col];
                bf[ni][1] = sb[(kk * 8 + tig + 4) * SB_STR + col];
            }
            #pragma unroll
            for (int mi = 0; mi < 4; mi++)
                #pragma unroll
                for (int ni = 0; ni < 4; ni++)
                    mma_tf32(acc[mi][ni], af[mi][0], af[mi][1], af[mi][2],
                             af[mi][3], bf[ni][0], bf[ni][1]);
        }

        __syncthreads();
        if (c + 1 < NCHUNK) {
            store_smem((c + 1) & 1, ra, rb);
            __syncthreads();
        }
    }

    // Epilogue: c0/c1 -> (row, 2*tig), c2/c3 -> (row+8, 2*tig); float2 stores
    #pragma unroll
    for (int mi = 0; mi < 4; mi++) {
        int r0 = bm + mrow0 + mi * 16 + g;
        #pragma unroll
        for (int ni = 0; ni < 4; ni++) {
            int col = bn + ncol0 + ni * 8 + 2 * tig;
            float2 bb = *(const float2*)&bias[col];
            float2 o0, o1;
            o0.x = acc[mi][ni][0] + bb.x;
            o0.y = acc[mi][ni][1] + bb.y;
            o1.x = acc[mi][ni][2] + bb.x;
            o1.y = acc[mi][ni][3] + bb.y;
            *(float2*)&C[(size_t)r0 * H_ + col] = o0;
            *(float2*)&C[(size_t)(r0 + 8) * H_ + col] = o1;
        }
    }
}

// ---------------------------------------------------------------------------
// Flash attention (unchanged from R1): per (batch, head), Br=128, Bc=64,
// online softmax. Mask is provably a no-op (uniform per-row shift).
// ---------------------------------------------------------------------------
__global__ __launch_bounds__(256) void attn_kernel(float* __restrict__ out)
{
    float* Qs = (float*)gsm;              // BR x PAD
    float* Ks = Qs + BR * PAD;            // BC x PAD
    float* Vs = Ks + BC * PAD;            // BC x PAD
    float* Ps = Vs + BC * PAD;            // BR x PAD

    const int tid = threadIdx.x;
    const int tx = tid & 15;
    const int ty = tid >> 4;
    const int b = blockIdx.z, h = blockIdx.y;
    const int q0 = blockIdx.x * BR;
    const float scale = 0.03125f;

    const float* Qg = g_Q + ((size_t)b * S_) * H_ + (size_t)h * HD_;
    const float* Kg = g_K + ((size_t)b * S_) * H_ + (size_t)h * HD_;
    const float* Vg = g_V + ((size_t)b * S_) * H_ + (size_t)h * HD_;

    #pragma unroll
    for (int it = 0; it < BR / 16; it++) {
        int r = (tid >> 4) + it * 16;
        int c = (tid & 15) * 4;
        float4 qv = *(const float4*)&Qg[(size_t)(q0 + r) * H_ + c];
        Qs[r * PAD + c + 0] = qv.x;
        Qs[r * PAD + c + 1] = qv.y;
        Qs[r * PAD + c + 2] = qv.z;
        Qs[r * PAD + c + 3] = qv.w;
    }

    float o[8][4] = {};
    float mrow[8], lrow[8];
    #pragma unroll
    for (int i = 0; i < 8; i++) { mrow[i] = -1e30f; lrow[i] = 0.0f; }

    for (int kt = 0; kt < S_; kt += BC) {
        __syncthreads();

        #pragma unroll
        for (int it = 0; it < BC / 16; it++) {
            int r = (tid >> 4) + it * 16;
            int c = (tid & 15) * 4;
            float4 kv = *(const float4*)&Kg[(size_t)(kt + r) * H_ + c];
            Ks[r * PAD + c + 0] = kv.x;
            Ks[r * PAD + c + 1] = kv.y;
            Ks[r * PAD + c + 2] = kv.z;
            Ks[r * PAD + c + 3] = kv.w;
            float4 vv = *(const float4*)&Vg[(size_t)(kt + r) * H_ + c];
            Vs[r * PAD + c + 0] = vv.x;
            Vs[r * PAD + c + 1] = vv.y;
            Vs[r * PAD + c + 2] = vv.z;
            Vs[r * PAD + c + 3] = vv.w;
        }
        __syncthreads();

        float s[8][4] = {};
        #pragma unroll 4
        for (int d = 0; d < HD_; d++) {
            float qa[8], kb[4];
            #pragma unroll
            for (int i = 0; i < 8; i++) qa[i] = Qs[(ty * 8 + i) * PAD + d];
            #pragma unroll
            for (int j = 0; j < 4; j++) kb[j] = Ks[(tx + 16 * j) * PAD + d];
            #pragma unroll
            for (int i = 0; i < 8; i++)
                #pragma unroll
                for (int j = 0; j < 4; j++)
                    s[i][j] = fmaf(qa[i], kb[j], s[i][j]);
        }

        #pragma unroll
        for (int i = 0; i < 8; i++) {
            #pragma unroll
            for (int j = 0; j < 4; j++) s[i][j] *= scale;
            float mt = fmaxf(fmaxf(s[i][0], s[i][1]), fmaxf(s[i][2], s[i][3]));
            #pragma unroll
            for (int off = 1; off < 16; off <<= 1)
                mt = fmaxf(mt, __shfl_xor_sync(0xffffffffu, mt, off));
            float mnew = fmaxf(mrow[i], mt);
            float corr = __expf(mrow[i] - mnew);
            mrow[i] = mnew;
            float rs = 0.0f;
            #pragma unroll
            for (int j = 0; j < 4; j++) {
                s[i][j] = __expf(s[i][j] - mnew);
                rs += s[i][j];
            }
            #pragma unroll
            for (int off = 1; off < 16; off <<= 1)
                rs += __shfl_xor_sync(0xffffffffu, rs, off);
            lrow[i] = lrow[i] * corr + rs;
            #pragma unroll
            for (int dd = 0; dd < 4; dd++) o[i][dd] *= corr;
            #pragma unroll
            for (int j = 0; j < 4; j++)
                Ps[(ty * 8 + i) * PAD + tx + 16 * j] = s[i][j];
        }
        __syncthreads();

        #pragma unroll 4
        for (int j = 0; j < BC; j++) {
            float pv[8], vb[4];
            #pragma unroll
            for (int i = 0; i < 8; i++) pv[i] = Ps[(ty * 8 + i) * PAD + j];
            #pragma unroll
            for (int dd = 0; dd < 4; dd++) vb[dd] = Vs[j * PAD + tx + 16 * dd];
            #pragma unroll
            for (int i = 0; i < 8; i++)
                #pragma unroll
                for (int dd = 0; dd < 4; dd++)
                    o[i][dd] = fmaf(pv[i], vb[dd], o[i][dd]);
        }
    }

    #pragma unroll
    for (int i = 0; i < 8; i++) {
        float inv = 1.0f / lrow[i];
        int r = q0 + ty * 8 + i;
        #pragma unroll
        for (int dd = 0; dd < 4; dd++)
            out[((size_t)b * S_ + r) * H_ + (size_t)h * HD_ + tx + 16 * dd] =
                o[i][dd] * inv;
    }
}

// ---------------------------------------------------------------------------
extern "C" void kernel_launch(void* const* d_in, const int* in_sizes, int n_in,
                              void* d_out, int out_size)
{
    const float* q  = (const float*)d_in[0];
    const float* k  = (const float*)d_in[1];
    const float* v  = (const float*)d_in[2];
    // d_in[3] = mask: no-op under softmax (uniform per-query-row shift)
    const float* wq = (const float*)d_in[4];
    const float* bq = (const float*)d_in[5];
    const float* wk = (const float*)d_in[6];
    const float* bk = (const float*)d_in[7];
    const float* wv = (const float*)d_in[8];
    const float* bv = (const float*)d_in[9];
    float* out = (float*)d_out;

    // QKV projections on tensor cores (mma.sync tf32)
    const int gemm_smem = (2 * TM * SA_STR + 2 * KC * SB_STR) * 4;  // ~70 KB
    cudaFuncSetAttribute(qkv_gemm_tc,
                         cudaFuncAttributeMaxDynamicSharedMemorySize, gemm_smem);
    dim3 gg(H_ / TN, M_ / TM, 3);
    qkv_gemm_tc<<<gg, 256, gemm_smem>>>(q, k, v, wq, bq, wk, bk, wv, bv);

    // Flash attention
    const int attn_smem = (BR * PAD + BC * PAD + BC * PAD + BR * PAD) * 4;
    cudaFuncSetAttribute(attn_kernel,
                         cudaFuncAttributeMaxDynamicSharedMemorySize, attn_smem);
    dim3 ga(S_ / BR, NH_, B_);
    attn_kernel<<<ga, 256, attn_smem>>>(out);
}

// round 4
// speedup vs baseline: 2.9572x; 2.2304x over previous
#include <cuda_runtime.h>
#include <cstdint>

#define B_   2
#define S_   2048
#define H_   1024
#define NH_  16
#define HD_  64
#define M_   (B_ * S_)

#define BR   128
#define BC   64

// GEMM tile config
#define TM   128
#define TN   128
#define KC   32
#define NCHUNK (H_ / KC)
#define SA_STR 36
#define SB_STR 136

// Attention SMEM strides (floats). 68 % 32 == 4 -> A/B frag banks 4g+tig
// unique; 72 % 32 == 8 -> V B-frag banks 8tig+g unique.
#define AQ_STR 68
#define AK_STR 68
#define AV_STR 72
#define AP_STR 68

// Scratch for projected Q/K/V (allocation-free rule: __device__ globals)
__device__ float g_Q[M_ * H_];
__device__ float g_K[M_ * H_];
__device__ float g_V[M_ * H_];

__device__ __forceinline__ uint32_t to_tf32(float x) {
    float r;
    asm("cvt.rna.tf32.f32 %0, %1;" : "=f"(r) : "f"(x));
    return __float_as_uint(r);
}

__device__ __forceinline__ void mma_tf32(float c[4], uint32_t a0, uint32_t a1,
                                         uint32_t a2, uint32_t a3,
                                         uint32_t b0, uint32_t b1) {
    asm volatile(
        "mma.sync.aligned.m16n8k8.row.col.f32.tf32.tf32.f32 "
        "{%0,%1,%2,%3}, {%4,%5,%6,%7}, {%8,%9}, {%0,%1,%2,%3};"
        : "+f"(c[0]), "+f"(c[1]), "+f"(c[2]), "+f"(c[3])
        : "r"(a0), "r"(a1), "r"(a2), "r"(a3), "r"(b0), "r"(b1));
}

extern __shared__ char gsm[];

// ---------------------------------------------------------------------------
// Tensor-core tf32 GEMM (unchanged from R3): C = A @ W + bias
// ---------------------------------------------------------------------------
__global__ __launch_bounds__(256) void qkv_gemm_tc(
    const float* __restrict__ q, const float* __restrict__ k,
    const float* __restrict__ v,
    const float* __restrict__ wq, const float* __restrict__ bq,
    const float* __restrict__ wk, const float* __restrict__ bk,
    const float* __restrict__ wv, const float* __restrict__ bv)
{
    const int which = blockIdx.z;
    const float* A    = (which == 0) ? q  : (which == 1) ? k  : v;
    const float* W    = (which == 0) ? wq : (which == 1) ? wk : wv;
    const float* bias = (which == 0) ? bq : (which == 1) ? bk : bv;
    float* C          = (which == 0) ? g_Q : (which == 1) ? g_K : g_V;

    uint32_t* As = (uint32_t*)gsm;
    uint32_t* Bs = As + 2 * TM * SA_STR;

    const int tid = threadIdx.x;
    const int wid = tid >> 5, lid = tid & 31;
    const int g = lid >> 2, tig = lid & 3;
    const int wr = wid >> 2, wc = wid & 3;
    const int mrow0 = wr * 64, ncol0 = wc * 32;
    const int bm = blockIdx.y * TM, bn = blockIdx.x * TN;

    float acc[4][4][4] = {};

    auto load_global = [&](int c, float4 ra[4], float4 rb[4]) {
        const int k0 = c * KC;
        #pragma unroll
        for (int i = 0; i < 4; i++) {
            int li = tid + i * 256;
            int m = li >> 3, kg = li & 7;
            ra[i] = *(const float4*)&A[(size_t)(bm + m) * H_ + k0 + kg * 4];
            int kr = li >> 5, ng = li & 31;
            rb[i] = *(const float4*)&W[(size_t)(k0 + kr) * H_ + bn + ng * 4];
        }
    };
    auto store_smem = [&](int buf, const float4 ra[4], const float4 rb[4]) {
        uint32_t* sa = As + buf * TM * SA_STR;
        uint32_t* sb = Bs + buf * KC * SB_STR;
        #pragma unroll
        for (int i = 0; i < 4; i++) {
            int li = tid + i * 256;
            int m = li >> 3, kg = li & 7;
            uint32_t* pa = sa + m * SA_STR + kg * 4;
            pa[0] = to_tf32(ra[i].x); pa[1] = to_tf32(ra[i].y);
            pa[2] = to_tf32(ra[i].z); pa[3] = to_tf32(ra[i].w);
            int kr = li >> 5, ng = li & 31;
            uint32_t* pb = sb + kr * SB_STR + ng * 4;
            pb[0] = to_tf32(rb[i].x); pb[1] = to_tf32(rb[i].y);
            pb[2] = to_tf32(rb[i].z); pb[3] = to_tf32(rb[i].w);
        }
    };

    {
        float4 ra[4], rb[4];
        load_global(0, ra, rb);
        store_smem(0, ra, rb);
    }
    __syncthreads();

    for (int c = 0; c < NCHUNK; c++) {
        const int buf = c & 1;
        const uint32_t* sa = As + buf * TM * SA_STR;
        const uint32_t* sb = Bs + buf * KC * SB_STR;

        float4 ra[4], rb[4];
        if (c + 1 < NCHUNK) load_global(c + 1, ra, rb);

        #pragma unroll
        for (int kk = 0; kk < 4; kk++) {
            uint32_t af[4][4];
            #pragma unroll
            for (int mi = 0; mi < 4; mi++) {
                int r = mrow0 + mi * 16 + g;
                int cb = kk * 8 + tig;
                af[mi][0] = sa[r * SA_STR + cb];
                af[mi][1] = sa[(r + 8) * SA_STR + cb];
                af[mi][2] = sa[r * SA_STR + cb + 4];
                af[mi][3] = sa[(r + 8) * SA_STR + cb + 4];
            }
            uint32_t bf[4][2];
            #pragma unroll
            for (int ni = 0; ni < 4; ni++) {
                int col = ncol0 + ni * 8 + g;
                bf[ni][0] = sb[(kk * 8 + tig) * SB_STR + col];
                bf[ni][1] = sb[(kk * 8 + tig + 4) * SB_STR + col];
            }
            #pragma unroll
            for (int mi = 0; mi < 4; mi++)
                #pragma unroll
                for (int ni = 0; ni < 4; ni++)
                    mma_tf32(acc[mi][ni], af[mi][0], af[mi][1], af[mi][2],
                             af[mi][3], bf[ni][0], bf[ni][1]);
        }

        __syncthreads();
        if (c + 1 < NCHUNK) {
            store_smem((c + 1) & 1, ra, rb);
            __syncthreads();
        }
    }

    #pragma unroll
    for (int mi = 0; mi < 4; mi++) {
        int r0 = bm + mrow0 + mi * 16 + g;
        #pragma unroll
        for (int ni = 0; ni < 4; ni++) {
            int col = bn + ncol0 + ni * 8 + 2 * tig;
            float2 bb = *(const float2*)&bias[col];
            float2 o0, o1;
            o0.x = acc[mi][ni][0] + bb.x;
            o0.y = acc[mi][ni][1] + bb.y;
            o1.x = acc[mi][ni][2] + bb.x;
            o1.y = acc[mi][ni][3] + bb.y;
            *(float2*)&C[(size_t)r0 * H_ + col] = o0;
            *(float2*)&C[(size_t)(r0 + 8) * H_ + col] = o1;
        }
    }
}

// ---------------------------------------------------------------------------
// Tensor-core flash attention. 8 warps x 16 q-rows; Bc=64 keys/tile.
// QK^T and PV on mma.sync tf32; online softmax in registers; each S-row is
// warp-private (quad shfl reductions only). Mask is a no-op (uniform shift).
// ---------------------------------------------------------------------------
__global__ __launch_bounds__(256) void attn_tc(float* __restrict__ out)
{
    uint32_t* Qs = (uint32_t*)gsm;            // [128][AQ_STR]
    uint32_t* Ks = Qs + BR * AQ_STR;          // [64][AK_STR]
    uint32_t* Vs = Ks + BC * AK_STR;          // [64][AV_STR]
    uint32_t* Ps = Vs + BC * AV_STR;          // [128][AP_STR]

    const int tid = threadIdx.x;
    const int wid = tid >> 5, lid = tid & 31;
    const int g = lid >> 2, tig = lid & 3;
    const int wrow = wid * 16;
    const int b = blockIdx.z, h = blockIdx.y;
    const int q0 = blockIdx.x * BR;
    const float scale = 0.03125f;             // 1/sqrt(1024)

    const float* Qg = g_Q + ((size_t)b * S_) * H_ + (size_t)h * HD_;
    const float* Kg = g_K + ((size_t)b * S_) * H_ + (size_t)h * HD_;
    const float* Vg = g_V + ((size_t)b * S_) * H_ + (size_t)h * HD_;

    // Load Q tile (tf32): 128x64
    #pragma unroll
    for (int i = 0; i < 8; i++) {
        int li = tid + i * 256;
        int r = li >> 4, c4 = (li & 15) * 4;
        float4 qv = *(const float4*)&Qg[(size_t)(q0 + r) * H_ + c4];
        uint32_t* p = Qs + r * AQ_STR + c4;
        p[0] = to_tf32(qv.x); p[1] = to_tf32(qv.y);
        p[2] = to_tf32(qv.z); p[3] = to_tf32(qv.w);
    }

    float o[8][4] = {};
    float m0 = -1e30f, m1 = -1e30f, l0 = 0.0f, l1 = 0.0f;

    for (int kt = 0; kt < S_; kt += BC) {
        __syncthreads();
        // Load K,V tiles (tf32): 64x64 each
        #pragma unroll
        for (int i = 0; i < 4; i++) {
            int li = tid + i * 256;
            int r = li >> 4, c4 = (li & 15) * 4;
            float4 kv = *(const float4*)&Kg[(size_t)(kt + r) * H_ + c4];
            uint32_t* pk = Ks + r * AK_STR + c4;
            pk[0] = to_tf32(kv.x); pk[1] = to_tf32(kv.y);
            pk[2] = to_tf32(kv.z); pk[3] = to_tf32(kv.w);
            float4 vv = *(const float4*)&Vg[(size_t)(kt + r) * H_ + c4];
            uint32_t* pv = Vs + r * AV_STR + c4;
            pv[0] = to_tf32(vv.x); pv[1] = to_tf32(vv.y);
            pv[2] = to_tf32(vv.z); pv[3] = to_tf32(vv.w);
        }
        __syncthreads();

        // S = Q @ K^T : rows wrow..wrow+15, cols 0..63
        float s[8][4] = {};
        #pragma unroll
        for (int kk = 0; kk < 8; kk++) {
            const int cb = kk * 8 + tig;
            uint32_t a0 = Qs[(wrow + g) * AQ_STR + cb];
            uint32_t a1 = Qs[(wrow + g + 8) * AQ_STR + cb];
            uint32_t a2 = Qs[(wrow + g) * AQ_STR + cb + 4];
            uint32_t a3 = Qs[(wrow + g + 8) * AQ_STR + cb + 4];
            #pragma unroll
            for (int ni = 0; ni < 8; ni++) {
                uint32_t b0 = Ks[(ni * 8 + g) * AK_STR + cb];
                uint32_t b1 = Ks[(ni * 8 + g) * AK_STR + cb + 4];
                mma_tf32(s[ni], a0, a1, a2, a3, b0, b1);
            }
        }

        // Online softmax. Row r=wrow+g: s[ni][0..1]; row r+8: s[ni][2..3].
        float mt0 = -1e30f, mt1 = -1e30f;
        #pragma unroll
        for (int ni = 0; ni < 8; ni++) {
            s[ni][0] *= scale; s[ni][1] *= scale;
            s[ni][2] *= scale; s[ni][3] *= scale;
            mt0 = fmaxf(mt0, fmaxf(s[ni][0], s[ni][1]));
            mt1 = fmaxf(mt1, fmaxf(s[ni][2], s[ni][3]));
        }
        #pragma unroll
        for (int off = 1; off < 4; off <<= 1) {
            mt0 = fmaxf(mt0, __shfl_xor_sync(0xffffffffu, mt0, off));
            mt1 = fmaxf(mt1, __shfl_xor_sync(0xffffffffu, mt1, off));
        }
        float mn0 = fmaxf(m0, mt0), mn1 = fmaxf(m1, mt1);
        float c0 = __expf(m0 - mn0), c1 = __expf(m1 - mn1);
        m0 = mn0; m1 = mn1;

        float rs0 = 0.0f, rs1 = 0.0f;
        #pragma unroll
        for (int ni = 0; ni < 8; ni++) {
            float p00 = __expf(s[ni][0] - mn0);
            float p01 = __expf(s[ni][1] - mn0);
            float p10 = __expf(s[ni][2] - mn1);
            float p11 = __expf(s[ni][3] - mn1);
            rs0 += p00 + p01;
            rs1 += p10 + p11;
            uint32_t* pr0 = Ps + (wrow + g) * AP_STR + ni * 8 + 2 * tig;
            uint32_t* pr1 = Ps + (wrow + g + 8) * AP_STR + ni * 8 + 2 * tig;
            pr0[0] = to_tf32(p00); pr0[1] = to_tf32(p01);
            pr1[0] = to_tf32(p10); pr1[1] = to_tf32(p11);
        }
        #pragma unroll
        for (int off = 1; off < 4; off <<= 1) {
            rs0 += __shfl_xor_sync(0xffffffffu, rs0, off);
            rs1 += __shfl_xor_sync(0xffffffffu, rs1, off);
        }
        l0 = l0 * c0 + rs0;
        l1 = l1 * c1 + rs1;
        #pragma unroll
        for (int ni = 0; ni < 8; ni++) {
            o[ni][0] *= c0; o[ni][1] *= c0;
            o[ni][2] *= c1; o[ni][3] *= c1;
        }
        __syncwarp();

        // O += P @ V
        #pragma unroll
        for (int kk = 0; kk < 8; kk++) {
            const int cb = kk * 8 + tig;
            uint32_t a0 = Ps[(wrow + g) * AP_STR + cb];
            uint32_t a1 = Ps[(wrow + g + 8) * AP_STR + cb];
            uint32_t a2 = Ps[(wrow + g) * AP_STR + cb + 4];
            uint32_t a3 = Ps[(wrow + g + 8) * AP_STR + cb + 4];
            #pragma unroll
            for (int ni = 0; ni < 8; ni++) {
                uint32_t b0 = Vs[cb * AV_STR + ni * 8 + g];
                uint32_t b1 = Vs[(cb + 4) * AV_STR + ni * 8 + g];
                mma_tf32(o[ni], a0, a1, a2, a3, b0, b1);
            }
        }
    }

    // Epilogue
    float inv0 = 1.0f / l0, inv1 = 1.0f / l1;
    const int r0 = q0 + wrow + g, r1 = r0 + 8;
    #pragma unroll
    for (int ni = 0; ni < 8; ni++) {
        int col = h * HD_ + ni * 8 + 2 * tig;
        float2 o0, o1;
        o0.x = o[ni][0] * inv0; o0.y = o[ni][1] * inv0;
        o1.x = o[ni][2] * inv1; o1.y = o[ni][3] * inv1;
        *(float2*)&out[((size_t)b * S_ + r0) * H_ + col] = o0;
        *(float2*)&out[((size_t)b * S_ + r1) * H_ + col] = o1;
    }
}

// ---------------------------------------------------------------------------
extern "C" void kernel_launch(void* const* d_in, const int* in_sizes, int n_in,
                              void* d_out, int out_size)
{
    const float* q  = (const float*)d_in[0];
    const float* k  = (const float*)d_in[1];
    const float* v  = (const float*)d_in[2];
    // d_in[3] = mask: no-op under softmax (uniform per-query-row shift)
    const float* wq = (const float*)d_in[4];
    const float* bq = (const float*)d_in[5];
    const float* wk = (const float*)d_in[6];
    const float* bk = (const float*)d_in[7];
    const float* wv = (const float*)d_in[8];
    const float* bv = (const float*)d_in[9];
    float* out = (float*)d_out;

    const int gemm_smem = (2 * TM * SA_STR + 2 * KC * SB_STR) * 4;
    cudaFuncSetAttribute(qkv_gemm_tc,
                         cudaFuncAttributeMaxDynamicSharedMemorySize, gemm_smem);
    dim3 gg(H_ / TN, M_ / TM, 3);
    qkv_gemm_tc<<<gg, 256, gemm_smem>>>(q, k, v, wq, bq, wk, bk, wv, bv);

    const int attn_smem =
        (BR * AQ_STR + BC * AK_STR + BC * AV_STR + BR * AP_STR) * 4;  // ~105.5 KB
    cudaFuncSetAttribute(attn_tc,
                         cudaFuncAttributeMaxDynamicSharedMemorySize, attn_smem);
    dim3 ga(S_ / BR, NH_, B_);
    attn_tc<<<ga, 256, attn_smem>>>(out);
}

// round 5
// speedup vs baseline: 3.2472x; 1.0981x over previous
#include <cuda_runtime.h>
#include <cstdint>

#define B_   2
#define S_   2048
#define H_   1024
#define NH_  16
#define HD_  64
#define M_   (B_ * S_)

#define BR   128
#define BC   64

// GEMM tile config
#define TM   128
#define TN   128
#define KC   32
#define NCHUNK (H_ / KC)
#define SA_STR 36
#define SB_STR 136

// Attention SMEM strides (floats). 68 % 32 == 4 -> Q/K/P frag banks 4g+tig
// unique; 72 % 32 == 8 -> V B-frag banks 8tig+g unique.
#define AQ_STR 68
#define AK_STR 68
#define AV_STR 72
#define AP_STR 68

// Scratch for projected Q/K/V (allocation-free rule: __device__ globals)
__device__ float g_Q[M_ * H_];
__device__ float g_K[M_ * H_];
__device__ float g_V[M_ * H_];

__device__ __forceinline__ uint32_t to_tf32(float x) {
    float r;
    asm("cvt.rna.tf32.f32 %0, %1;" : "=f"(r) : "f"(x));
    return __float_as_uint(r);
}

__device__ __forceinline__ void mma_tf32(float c[4], uint32_t a0, uint32_t a1,
                                         uint32_t a2, uint32_t a3,
                                         uint32_t b0, uint32_t b1) {
    asm volatile(
        "mma.sync.aligned.m16n8k8.row.col.f32.tf32.tf32.f32 "
        "{%0,%1,%2,%3}, {%4,%5,%6,%7}, {%8,%9}, {%0,%1,%2,%3};"
        : "+f"(c[0]), "+f"(c[1]), "+f"(c[2]), "+f"(c[3])
        : "r"(a0), "r"(a1), "r"(a2), "r"(a3), "r"(b0), "r"(b1));
}

extern __shared__ char gsm[];

// ---------------------------------------------------------------------------
// Tensor-core tf32 GEMM: C = A @ W + bias (one redundant sync removed)
// ---------------------------------------------------------------------------
__global__ __launch_bounds__(256) void qkv_gemm_tc(
    const float* __restrict__ q, const float* __restrict__ k,
    const float* __restrict__ v,
    const float* __restrict__ wq, const float* __restrict__ bq,
    const float* __restrict__ wk, const float* __restrict__ bk,
    const float* __restrict__ wv, const float* __restrict__ bv)
{
    const int which = blockIdx.z;
    const float* A    = (which == 0) ? q  : (which == 1) ? k  : v;
    const float* W    = (which == 0) ? wq : (which == 1) ? wk : wv;
    const float* bias = (which == 0) ? bq : (which == 1) ? bk : bv;
    float* C          = (which == 0) ? g_Q : (which == 1) ? g_K : g_V;

    uint32_t* As = (uint32_t*)gsm;
    uint32_t* Bs = As + 2 * TM * SA_STR;

    const int tid = threadIdx.x;
    const int wid = tid >> 5, lid = tid & 31;
    const int g = lid >> 2, tig = lid & 3;
    const int wr = wid >> 2, wc = wid & 3;
    const int mrow0 = wr * 64, ncol0 = wc * 32;
    const int bm = blockIdx.y * TM, bn = blockIdx.x * TN;

    float acc[4][4][4] = {};

    auto load_global = [&](int c, float4 ra[4], float4 rb[4]) {
        const int k0 = c * KC;
        #pragma unroll
        for (int i = 0; i < 4; i++) {
            int li = tid + i * 256;
            int m = li >> 3, kg = li & 7;
            ra[i] = *(const float4*)&A[(size_t)(bm + m) * H_ + k0 + kg * 4];
            int kr = li >> 5, ng = li & 31;
            rb[i] = *(const float4*)&W[(size_t)(k0 + kr) * H_ + bn + ng * 4];
        }
    };
    auto store_smem = [&](int buf, const float4 ra[4], const float4 rb[4]) {
        uint32_t* sa = As + buf * TM * SA_STR;
        uint32_t* sb = Bs + buf * KC * SB_STR;
        #pragma unroll
        for (int i = 0; i < 4; i++) {
            int li = tid + i * 256;
            int m = li >> 3, kg = li & 7;
            uint32_t* pa = sa + m * SA_STR + kg * 4;
            pa[0] = to_tf32(ra[i].x); pa[1] = to_tf32(ra[i].y);
            pa[2] = to_tf32(ra[i].z); pa[3] = to_tf32(ra[i].w);
            int kr = li >> 5, ng = li & 31;
            uint32_t* pb = sb + kr * SB_STR + ng * 4;
            pb[0] = to_tf32(rb[i].x); pb[1] = to_tf32(rb[i].y);
            pb[2] = to_tf32(rb[i].z); pb[3] = to_tf32(rb[i].w);
        }
    };

    {
        float4 ra[4], rb[4];
        load_global(0, ra, rb);
        store_smem(0, ra, rb);
    }
    __syncthreads();

    for (int c = 0; c < NCHUNK; c++) {
        const int buf = c & 1;
        const uint32_t* sa = As + buf * TM * SA_STR;
        const uint32_t* sb = Bs + buf * KC * SB_STR;

        float4 ra[4], rb[4];
        if (c + 1 < NCHUNK) load_global(c + 1, ra, rb);

        #pragma unroll
        for (int kk = 0; kk < 4; kk++) {
            uint32_t af[4][4];
            #pragma unroll
            for (int mi = 0; mi < 4; mi++) {
                int r = mrow0 + mi * 16 + g;
                int cb = kk * 8 + tig;
                af[mi][0] = sa[r * SA_STR + cb];
                af[mi][1] = sa[(r + 8) * SA_STR + cb];
                af[mi][2] = sa[r * SA_STR + cb + 4];
                af[mi][3] = sa[(r + 8) * SA_STR + cb + 4];
            }
            uint32_t bf[4][2];
            #pragma unroll
            for (int ni = 0; ni < 4; ni++) {
                int col = ncol0 + ni * 8 + g;
                bf[ni][0] = sb[(kk * 8 + tig) * SB_STR + col];
                bf[ni][1] = sb[(kk * 8 + tig + 4) * SB_STR + col];
            }
            #pragma unroll
            for (int mi = 0; mi < 4; mi++)
                #pragma unroll
                for (int ni = 0; ni < 4; ni++)
                    mma_tf32(acc[mi][ni], af[mi][0], af[mi][1], af[mi][2],
                             af[mi][3], bf[ni][0], bf[ni][1]);
        }

        // Single sync: the buffer being stored next was last read in chunk
        // c-1, which is already separated from here by the previous sync.
        if (c + 1 < NCHUNK) {
            store_smem((c + 1) & 1, ra, rb);
            __syncthreads();
        }
    }

    #pragma unroll
    for (int mi = 0; mi < 4; mi++) {
        int r0 = bm + mrow0 + mi * 16 + g;
        #pragma unroll
        for (int ni = 0; ni < 4; ni++) {
            int col = bn + ncol0 + ni * 8 + 2 * tig;
            float2 bb = *(const float2*)&bias[col];
            float2 o0, o1;
            o0.x = acc[mi][ni][0] + bb.x;
            o0.y = acc[mi][ni][1] + bb.y;
            o1.x = acc[mi][ni][2] + bb.x;
            o1.y = acc[mi][ni][3] + bb.y;
            *(float2*)&C[(size_t)r0 * H_ + col] = o0;
            *(float2*)&C[(size_t)(r0 + 8) * H_ + col] = o1;
        }
    }
}

// ---------------------------------------------------------------------------
// Tensor-core flash attention, v2: 4 warps x 32 q-rows (mi=2 blocks of 16).
// K/V b-fragments loaded once per (kk,ni) and reused across both mi blocks,
// halving K/V crossbar bytes per q-row. Mask is a no-op (uniform shift).
// ---------------------------------------------------------------------------
__global__ __launch_bounds__(128) void attn_tc(float* __restrict__ out)
{
    uint32_t* Qs = (uint32_t*)gsm;            // [128][AQ_STR]
    uint32_t* Ks = Qs + BR * AQ_STR;          // [64][AK_STR]
    uint32_t* Vs = Ks + BC * AK_STR;          // [64][AV_STR]
    uint32_t* Ps = Vs + BC * AV_STR;          // [128][AP_STR]

    const int tid = threadIdx.x;
    const int wid = tid >> 5, lid = tid & 31;
    const int g = lid >> 2, tig = lid & 3;
    const int wrow = wid * 32;                // 32 q-rows per warp
    const int b = blockIdx.z, h = blockIdx.y;
    const int q0 = blockIdx.x * BR;
    const float scale = 0.03125f;             // 1/sqrt(1024)

    const float* Qg = g_Q + ((size_t)b * S_) * H_ + (size_t)h * HD_;
    const float* Kg = g_K + ((size_t)b * S_) * H_ + (size_t)h * HD_;
    const float* Vg = g_V + ((size_t)b * S_) * H_ + (size_t)h * HD_;

    // Load Q tile (tf32): 128x64, 128 threads
    #pragma unroll
    for (int i = 0; i < 16; i++) {
        int li = tid + i * 128;
        int r = li >> 4, c4 = (li & 15) * 4;
        float4 qv = *(const float4*)&Qg[(size_t)(q0 + r) * H_ + c4];
        uint32_t* p = Qs + r * AQ_STR + c4;
        p[0] = to_tf32(qv.x); p[1] = to_tf32(qv.y);
        p[2] = to_tf32(qv.z); p[3] = to_tf32(qv.w);
    }

    float o[2][8][4] = {};
    float m0[2], m1[2], l0[2], l1[2];
    #pragma unroll
    for (int mi = 0; mi < 2; mi++) {
        m0[mi] = -1e30f; m1[mi] = -1e30f; l0[mi] = 0.0f; l1[mi] = 0.0f;
    }

    for (int kt = 0; kt < S_; kt += BC) {
        __syncthreads();
        // Load K,V tiles (tf32): 64x64 each, 128 threads
        #pragma unroll
        for (int i = 0; i < 8; i++) {
            int li = tid + i * 128;
            int r = li >> 4, c4 = (li & 15) * 4;
            float4 kv = *(const float4*)&Kg[(size_t)(kt + r) * H_ + c4];
            uint32_t* pk = Ks + r * AK_STR + c4;
            pk[0] = to_tf32(kv.x); pk[1] = to_tf32(kv.y);
            pk[2] = to_tf32(kv.z); pk[3] = to_tf32(kv.w);
            float4 vv = *(const float4*)&Vg[(size_t)(kt + r) * H_ + c4];
            uint32_t* pv = Vs + r * AV_STR + c4;
            pv[0] = to_tf32(vv.x); pv[1] = to_tf32(vv.y);
            pv[2] = to_tf32(vv.z); pv[3] = to_tf32(vv.w);
        }
        __syncthreads();

        // S = Q @ K^T : 32 rows x 64 cols per warp; K frags shared across mi
        float s[2][8][4] = {};
        #pragma unroll
        for (int kk = 0; kk < 8; kk++) {
            const int cb = kk * 8 + tig;
            uint32_t a[2][4];
            #pragma unroll
            for (int mi = 0; mi < 2; mi++) {
                int r = wrow + mi * 16 + g;
                a[mi][0] = Qs[r * AQ_STR + cb];
                a[mi][1] = Qs[(r + 8) * AQ_STR + cb];
                a[mi][2] = Qs[r * AQ_STR + cb + 4];
                a[mi][3] = Qs[(r + 8) * AQ_STR + cb + 4];
            }
            #pragma unroll
            for (int ni = 0; ni < 8; ni++) {
                uint32_t b0 = Ks[(ni * 8 + g) * AK_STR + cb];
                uint32_t b1 = Ks[(ni * 8 + g) * AK_STR + cb + 4];
                mma_tf32(s[0][ni], a[0][0], a[0][1], a[0][2], a[0][3], b0, b1);
                mma_tf32(s[1][ni], a[1][0], a[1][1], a[1][2], a[1][3], b0, b1);
            }
        }

        // Online softmax per mi block; rows wrow+mi*16+g and +8
        #pragma unroll
        for (int mi = 0; mi < 2; mi++) {
            float mt0 = -1e30f, mt1 = -1e30f;
            #pragma unroll
            for (int ni = 0; ni < 8; ni++) {
                s[mi][ni][0] *= scale; s[mi][ni][1] *= scale;
                s[mi][ni][2] *= scale; s[mi][ni][3] *= scale;
                mt0 = fmaxf(mt0, fmaxf(s[mi][ni][0], s[mi][ni][1]));
                mt1 = fmaxf(mt1, fmaxf(s[mi][ni][2], s[mi][ni][3]));
            }
            #pragma unroll
            for (int off = 1; off < 4; off <<= 1) {
                mt0 = fmaxf(mt0, __shfl_xor_sync(0xffffffffu, mt0, off));
                mt1 = fmaxf(mt1, __shfl_xor_sync(0xffffffffu, mt1, off));
            }
            float mn0 = fmaxf(m0[mi], mt0), mn1 = fmaxf(m1[mi], mt1);
            float c0 = __expf(m0[mi] - mn0), c1 = __expf(m1[mi] - mn1);
            m0[mi] = mn0; m1[mi] = mn1;

            float rs0 = 0.0f, rs1 = 0.0f;
            #pragma unroll
            for (int ni = 0; ni < 8; ni++) {
                float p00 = __expf(s[mi][ni][0] - mn0);
                float p01 = __expf(s[mi][ni][1] - mn0);
                float p10 = __expf(s[mi][ni][2] - mn1);
                float p11 = __expf(s[mi][ni][3] - mn1);
                rs0 += p00 + p01;
                rs1 += p10 + p11;
                int r = wrow + mi * 16 + g;
                uint32_t* pr0 = Ps + r * AP_STR + ni * 8 + 2 * tig;
                uint32_t* pr1 = Ps + (r + 8) * AP_STR + ni * 8 + 2 * tig;
                pr0[0] = to_tf32(p00); pr0[1] = to_tf32(p01);
                pr1[0] = to_tf32(p10); pr1[1] = to_tf32(p11);
            }
            #pragma unroll
            for (int off = 1; off < 4; off <<= 1) {
                rs0 += __shfl_xor_sync(0xffffffffu, rs0, off);
                rs1 += __shfl_xor_sync(0xffffffffu, rs1, off);
            }
            l0[mi] = l0[mi] * c0 + rs0;
            l1[mi] = l1[mi] * c1 + rs1;
            #pragma unroll
            for (int ni = 0; ni < 8; ni++) {
                o[mi][ni][0] *= c0; o[mi][ni][1] *= c0;
                o[mi][ni][2] *= c1; o[mi][ni][3] *= c1;
            }
        }
        __syncwarp();

        // O += P @ V ; V frags shared across mi
        #pragma unroll
        for (int kk = 0; kk < 8; kk++) {
            const int cb = kk * 8 + tig;
            uint32_t a[2][4];
            #pragma unroll
            for (int mi = 0; mi < 2; mi++) {
                int r = wrow + mi * 16 + g;
                a[mi][0] = Ps[r * AP_STR + cb];
                a[mi][1] = Ps[(r + 8) * AP_STR + cb];
                a[mi][2] = Ps[r * AP_STR + cb + 4];
                a[mi][3] = Ps[(r + 8) * AP_STR + cb + 4];
            }
            #pragma unroll
            for (int ni = 0; ni < 8; ni++) {
                uint32_t b0 = Vs[cb * AV_STR + ni * 8 + g];
                uint32_t b1 = Vs[(cb + 4) * AV_STR + ni * 8 + g];
                mma_tf32(o[0][ni], a[0][0], a[0][1], a[0][2], a[0][3], b0, b1);
                mma_tf32(o[1][ni], a[1][0], a[1][1], a[1][2], a[1][3], b0, b1);
            }
        }
    }

    // Epilogue
    #pragma unroll
    for (int mi = 0; mi < 2; mi++) {
        float inv0 = 1.0f / l0[mi], inv1 = 1.0f / l1[mi];
        const int r0 = q0 + wrow + mi * 16 + g, r1 = r0 + 8;
        #pragma unroll
        for (int ni = 0; ni < 8; ni++) {
            int col = h * HD_ + ni * 8 + 2 * tig;
            float2 o0, o1;
            o0.x = o[mi][ni][0] * inv0; o0.y = o[mi][ni][1] * inv0;
            o1.x = o[mi][ni][2] * inv1; o1.y = o[mi][ni][3] * inv1;
            *(float2*)&out[((size_t)b * S_ + r0) * H_ + col] = o0;
            *(float2*)&out[((size_t)b * S_ + r1) * H_ + col] = o1;
        }
    }
}

// ---------------------------------------------------------------------------
extern "C" void kernel_launch(void* const* d_in, const int* in_sizes, int n_in,
                              void* d_out, int out_size)
{
    const float* q  = (const float*)d_in[0];
    const float* k  = (const float*)d_in[1];
    const float* v  = (const float*)d_in[2];
    // d_in[3] = mask: no-op under softmax (uniform per-query-row shift)
    const float* wq = (const float*)d_in[4];
    const float* bq = (const float*)d_in[5];
    const float* wk = (const float*)d_in[6];
    const float* bk = (const float*)d_in[7];
    const float* wv = (const float*)d_in[8];
    const float* bv = (const float*)d_in[9];
    float* out = (float*)d_out;

    const int gemm_smem = (2 * TM * SA_STR + 2 * KC * SB_STR) * 4;
    cudaFuncSetAttribute(qkv_gemm_tc,
                         cudaFuncAttributeMaxDynamicSharedMemorySize, gemm_smem);
    dim3 gg(H_ / TN, M_ / TM, 3);
    qkv_gemm_tc<<<gg, 256, gemm_smem>>>(q, k, v, wq, bq, wk, bk, wv, bv);

    const int attn_smem =
        (BR * AQ_STR + BC * AK_STR + BC * AV_STR + BR * AP_STR) * 4;  // ~105.5 KB
    cudaFuncSetAttribute(attn_tc,
                         cudaFuncAttributeMaxDynamicSharedMemorySize, attn_smem);
    dim3 ga(S_ / BR, NH_, B_);
    attn_tc<<<ga, 128, attn_smem>>>(out);
}